// round 1
// baseline (speedup 1.0000x reference)
#include <cuda_runtime.h>
#include <cstdint>

// ---------------------------------------------------------------------------
// LinearAttention: out = ((elu(xWq+bq)+1) applied to linear attention with
// K,V summarization) @ Wo + bo
// B=4, S=4096, D=1024, H=16, hd=64
// Round 1: fp32 FFMA baseline. GEMMs dominate (137 GFLOP).
// ---------------------------------------------------------------------------

#define BATCH 4
#define SEQ   4096
#define EMB   1024
#define HEADS 16
#define HDIM  64
#define ROWS  (BATCH * SEQ)     // 16384
#define BH    (BATCH * HEADS)   // 64
#define SPLITS 8
#define SROWS (SEQ / SPLITS)    // 512

// Scratch (static device arrays: allocation-free per harness rules)
__device__ float g_Q[(size_t)ROWS * EMB];
__device__ float g_K[(size_t)ROWS * EMB];
__device__ float g_V[(size_t)ROWS * EMB];
__device__ float g_attn[(size_t)ROWS * EMB];
__device__ float g_KVp[(size_t)SPLITS * BH * HDIM * HDIM];
__device__ float g_Ksump[(size_t)SPLITS * BH * HDIM];
__device__ float g_KV[(size_t)BH * HDIM * HDIM];
__device__ float g_Ksum[(size_t)BH * HDIM];

// ---------------------------------------------------------------------------
// SGEMM: C[M,N] = A[M,K] @ B[K,N] + bias (+ optional elu+1)
// Block tile 128x128, K-tile 8, 256 threads, 8x8 per thread.
// M=16384, N=1024, K=1024 (all divisible; no bounds checks).
// ---------------------------------------------------------------------------
#define BM 128
#define BN 128
#define BK 8
#define TM 8
#define TN 8

__global__ __launch_bounds__(256, 2) void sgemm_bias(
    const float* __restrict__ A, const float* __restrict__ B,
    const float* __restrict__ bias, float* __restrict__ C,
    int M, int N, int K, int elu_mode)
{
    __shared__ float As[BK][BM];
    __shared__ float Bs[BK][BN];

    const int bn = blockIdx.x;
    const int bm = blockIdx.y;
    const int t  = threadIdx.x;
    const int tx = t % 16;
    const int ty = t / 16;

    const float* Ablk = A + (size_t)bm * BM * K;
    const float* Bblk = B + (size_t)bn * BN;

    // global-load indices
    const int arow = t >> 1;           // 0..127
    const int acol = (t & 1) * 4;      // 0 or 4
    const int brow = t >> 5;           // 0..7
    const int bcol = (t & 31) * 4;     // 0..124

    float acc[TM][TN];
    #pragma unroll
    for (int i = 0; i < TM; i++)
        #pragma unroll
        for (int j = 0; j < TN; j++) acc[i][j] = 0.f;

    for (int k0 = 0; k0 < K; k0 += BK) {
        float4 av = *(const float4*)(Ablk + (size_t)arow * K + k0 + acol);
        As[acol + 0][arow] = av.x;
        As[acol + 1][arow] = av.y;
        As[acol + 2][arow] = av.z;
        As[acol + 3][arow] = av.w;
        float4 bv = *(const float4*)(Bblk + (size_t)(k0 + brow) * N + bcol);
        *(float4*)&Bs[brow][bcol] = bv;
        __syncthreads();

        #pragma unroll
        for (int kk = 0; kk < BK; kk++) {
            float a[TM], b[TN];
            #pragma unroll
            for (int i = 0; i < TM; i++) a[i] = As[kk][ty * TM + i];
            #pragma unroll
            for (int j = 0; j < TN; j++) b[j] = Bs[kk][tx * TN + j];
            #pragma unroll
            for (int i = 0; i < TM; i++)
                #pragma unroll
                for (int j = 0; j < TN; j++)
                    acc[i][j] += a[i] * b[j];
        }
        __syncthreads();
    }

    const int crow0 = bm * BM + ty * TM;
    const int ccol0 = bn * BN + tx * TN;
    float bvals[TN];
    #pragma unroll
    for (int j = 0; j < TN; j++) bvals[j] = bias[ccol0 + j];

    #pragma unroll
    for (int i = 0; i < TM; i++) {
        float4 o0, o1;
        float* op = (float*)&o0;
        #pragma unroll
        for (int j = 0; j < TN; j++) {
            float v = acc[i][j] + bvals[j];
            if (elu_mode) v = (v > 0.f) ? (v + 1.f) : expf(v);
            if (j < 4) ((float*)&o0)[j] = v; else ((float*)&o1)[j - 4] = v;
        }
        (void)op;
        float* cp = C + (size_t)(crow0 + i) * N + ccol0;
        *(float4*)cp       = o0;
        *(float4*)(cp + 4) = o1;
    }
}

// ---------------------------------------------------------------------------
// KV summarization (partial): KV[b,h,d,e] = sum_s K[b,s,h,d] * V[b,s,h,e]
// and Ksum[b,h,d] = sum_s K[b,s,h,d].  Split over S for parallelism;
// deterministic two-stage reduction (no atomics).
// ---------------------------------------------------------------------------
#define KVCHUNK 8

__global__ __launch_bounds__(256) void kv_partial()
{
    const int bh = blockIdx.x;          // 0..63
    const int sp = blockIdx.y;          // 0..SPLITS-1
    const int b = bh / HEADS, h = bh % HEADS;
    const int t = threadIdx.x;
    const int d = t & 63;               // 0..63
    const int g = t >> 6;               // 0..3  -> e range [g*16, g*16+16)

    __shared__ float Ks[KVCHUNK][HDIM];
    __shared__ float Vs[KVCHUNK][HDIM];

    float acc[16];
    #pragma unroll
    for (int j = 0; j < 16; j++) acc[j] = 0.f;
    float ksum = 0.f;

    const float* Kbase = g_K + (size_t)b * SEQ * EMB + h * HDIM;
    const float* Vbase = g_V + (size_t)b * SEQ * EMB + h * HDIM;

    const int s_begin = sp * SROWS;
    for (int s0 = s_begin; s0 < s_begin + SROWS; s0 += KVCHUNK) {
        #pragma unroll
        for (int k = 0; k < (KVCHUNK * HDIM) / 256; k++) {  // 2 iters
            int idx = t + 256 * k;
            int rr = idx >> 6, cc = idx & 63;
            Ks[rr][cc] = Kbase[(size_t)(s0 + rr) * EMB + cc];
            Vs[rr][cc] = Vbase[(size_t)(s0 + rr) * EMB + cc];
        }
        __syncthreads();
        #pragma unroll
        for (int ss = 0; ss < KVCHUNK; ss++) {
            float kd = Ks[ss][d];
            if (g == 0) ksum += kd;
            #pragma unroll
            for (int j = 0; j < 16; j++)
                acc[j] += kd * Vs[ss][g * 16 + j];
        }
        __syncthreads();
    }

    float* KVp = g_KVp + ((size_t)sp * BH + bh) * HDIM * HDIM;
    #pragma unroll
    for (int j = 0; j < 16; j++)
        KVp[d * HDIM + g * 16 + j] = acc[j];
    if (g == 0) g_Ksump[((size_t)sp * BH + bh) * HDIM + d] = ksum;
}

__global__ __launch_bounds__(256) void kv_reduce()
{
    const int bh = blockIdx.x;
    const int t = threadIdx.x;
    for (int i = t; i < HDIM * HDIM; i += 256) {
        float s = 0.f;
        #pragma unroll
        for (int sp = 0; sp < SPLITS; sp++)
            s += g_KVp[((size_t)sp * BH + bh) * HDIM * HDIM + i];
        g_KV[(size_t)bh * HDIM * HDIM + i] = s;
    }
    if (t < HDIM) {
        float s = 0.f;
        #pragma unroll
        for (int sp = 0; sp < SPLITS; sp++)
            s += g_Ksump[((size_t)sp * BH + bh) * HDIM + t];
        g_Ksum[(size_t)bh * HDIM + t] = s;
    }
}

// ---------------------------------------------------------------------------
// Apply: attn[b,s,h,e] = (sum_d Q[b,s,h,d]*KV[b,h,d,e]) / (sum_d Q*Ksum + 1e-6)
// One block per (64-row S tile, bh). KV tile + Q tile staged in shared.
// ---------------------------------------------------------------------------
__global__ __launch_bounds__(256) void apply_attn()
{
    const int stile = blockIdx.x;       // 0..63
    const int bh = blockIdx.y;          // 0..63
    const int b = bh / HEADS, h = bh % HEADS;
    const int t = threadIdx.x;

    __shared__ float Qs[64][HDIM];
    __shared__ float KVs[HDIM][HDIM];
    __shared__ float Ksums[HDIM];

    const int s0 = stile * 64;
    const float* Qbase = g_Q + (size_t)(b * SEQ + s0) * EMB + h * HDIM;

    #pragma unroll
    for (int k = 0; k < 16; k++) {
        int idx = t + 256 * k;
        int rr = idx >> 6, cc = idx & 63;
        Qs[rr][cc] = Qbase[(size_t)rr * EMB + cc];
        KVs[rr][cc] = g_KV[(size_t)bh * HDIM * HDIM + idx];
    }
    if (t < HDIM) Ksums[t] = g_Ksum[(size_t)bh * HDIM + t];
    __syncthreads();

    const int row = t >> 2;             // 0..63
    const int e0 = (t & 3) * 16;        // 0,16,32,48

    float acc[16];
    #pragma unroll
    for (int j = 0; j < 16; j++) acc[j] = 0.f;
    float norm = 0.f;

    #pragma unroll
    for (int dd = 0; dd < HDIM; dd++) {
        float qd = Qs[row][dd];
        norm += qd * Ksums[dd];
        #pragma unroll
        for (int j = 0; j < 16; j++)
            acc[j] += qd * KVs[dd][e0 + j];
    }

    float inv = 1.f / (norm + 1e-6f);
    float* outp = g_attn + (size_t)(b * SEQ + s0 + row) * EMB + h * HDIM + e0;
    #pragma unroll
    for (int j = 0; j < 16; j += 4) {
        float4 o;
        o.x = acc[j + 0] * inv; o.y = acc[j + 1] * inv;
        o.z = acc[j + 2] * inv; o.w = acc[j + 3] * inv;
        *(float4*)(outp + j) = o;
    }
}

// ---------------------------------------------------------------------------
// Launch
// ---------------------------------------------------------------------------
extern "C" void kernel_launch(void* const* d_in, const int* in_sizes, int n_in,
                              void* d_out, int out_size)
{
    const float* query = (const float*)d_in[0];
    const float* keyv  = (const float*)d_in[1];
    const float* Wq = (const float*)d_in[2];
    const float* bq = (const float*)d_in[3];
    const float* Wk = (const float*)d_in[4];
    const float* bk = (const float*)d_in[5];
    const float* Wv = (const float*)d_in[6];
    const float* bv = (const float*)d_in[7];
    const float* Wo = (const float*)d_in[8];
    const float* bo = (const float*)d_in[9];
    float* out = (float*)d_out;

    float *pQ, *pK, *pV, *pA;
    cudaGetSymbolAddress((void**)&pQ, g_Q);
    cudaGetSymbolAddress((void**)&pK, g_K);
    cudaGetSymbolAddress((void**)&pV, g_V);
    cudaGetSymbolAddress((void**)&pA, g_attn);

    dim3 gemm_grid(EMB / BN, ROWS / BM);   // (8, 128)

    // Projections (Q,K get elu+1 fused)
    sgemm_bias<<<gemm_grid, 256>>>(query, Wq, bq, pQ, ROWS, EMB, EMB, 1);
    sgemm_bias<<<gemm_grid, 256>>>(keyv,  Wk, bk, pK, ROWS, EMB, EMB, 1);
    sgemm_bias<<<gemm_grid, 256>>>(keyv,  Wv, bv, pV, ROWS, EMB, EMB, 0);

    // KV summarization (split + deterministic reduce)
    kv_partial<<<dim3(BH, SPLITS), 256>>>();
    kv_reduce<<<BH, 256>>>();

    // Attention apply
    apply_attn<<<dim3(SEQ / 64, BH), 256>>>();

    // Output projection
    sgemm_bias<<<gemm_grid, 256>>>(pA, Wo, bo, out, ROWS, EMB, EMB, 0);
}

// round 4
// speedup vs baseline: 2.0378x; 2.0378x over previous
#include <cuda_runtime.h>
#include <cuda_bf16.h>
#include <cstdint>

// ---------------------------------------------------------------------------
// LinearAttention on GB300 (sm_103a via compute_103 PTX)
// Round 4: mma.sync.m16n8k16 bf16 hi/lo split GEMMs.
// tcgen05 is NOT available through this harness (PTX virtual arch compute_103
// rejects all tcgen05.*) — legacy HMMA via mma.sync is the tensor path.
// B=4, S=4096, D=1024, H=16, hd=64
// ---------------------------------------------------------------------------

#define BATCH 4
#define SEQ   4096
#define EMB   1024
#define HEADS 16
#define HDIM  64
#define ROWS  (BATCH * SEQ)     // 16384
#define BH    (BATCH * HEADS)   // 64
#define SPLITS 16
#define SROWS (SEQ / SPLITS)    // 256

// GEMM tiling
#define MT 128
#define NTT 128
#define KC 32
#define KCH (EMB / KC)          // 32
#define STAGES 3
#define G_THREADS 256
// smem stage layout (bf16 rows padded 32->40 elems = 80B pitch)
#define PITCH 40
#define PITCHB 80
#define SZ_ONE (MT * PITCHB)            // 10240 B  (one 128x32 tile)
#define OFF_AH 0
#define OFF_AL (SZ_ONE)
#define OFF_BH (2 * SZ_ONE)
#define OFF_BL (3 * SZ_ONE)
#define STAGE_BYTES (4 * SZ_ONE)        // 40960
#define SMEM_DYN (STAGES * STAGE_BYTES) // 122880

// ---------------------------------------------------------------------------
// Scratch (__device__ globals; allocation-free per harness rules)
// ---------------------------------------------------------------------------
__device__ __align__(256) float g_Q[(size_t)ROWS * EMB];
__device__ __align__(256) float g_K[(size_t)ROWS * EMB];
__device__ __align__(256) float g_V[(size_t)ROWS * EMB];
__device__ __align__(256) __nv_bfloat16 g_Xhi[(size_t)ROWS * EMB];
__device__ __align__(256) __nv_bfloat16 g_Xlo[(size_t)ROWS * EMB];
__device__ __align__(256) __nv_bfloat16 g_Wqh[(size_t)EMB * EMB];
__device__ __align__(256) __nv_bfloat16 g_Wql[(size_t)EMB * EMB];
__device__ __align__(256) __nv_bfloat16 g_Wkh[(size_t)EMB * EMB];
__device__ __align__(256) __nv_bfloat16 g_Wkl[(size_t)EMB * EMB];
__device__ __align__(256) __nv_bfloat16 g_Wvh[(size_t)EMB * EMB];
__device__ __align__(256) __nv_bfloat16 g_Wvl[(size_t)EMB * EMB];
__device__ __align__(256) __nv_bfloat16 g_Woh[(size_t)EMB * EMB];
__device__ __align__(256) __nv_bfloat16 g_Wol[(size_t)EMB * EMB];
__device__ float g_KVp[(size_t)SPLITS * BH * HDIM * HDIM];
__device__ float g_Ksump[(size_t)SPLITS * BH * HDIM];
__device__ float g_KV[(size_t)BH * HDIM * HDIM];
__device__ float g_Ksum[(size_t)BH * HDIM];

// ---------------------------------------------------------------------------
// PTX helpers (compute_103-safe: cp.async, ldmatrix, mma.sync only)
// ---------------------------------------------------------------------------
__device__ __forceinline__ uint32_t smem_u32(const void* p) {
    uint32_t a;
    asm("{ .reg .u64 t; cvta.to.shared.u64 t, %1; cvt.u32.u64 %0, t; }" : "=r"(a) : "l"(p));
    return a;
}
__device__ __forceinline__ void cp16(uint32_t saddr, const void* gaddr) {
    asm volatile("cp.async.cg.shared.global [%0], [%1], 16;" :: "r"(saddr), "l"(gaddr) : "memory");
}
__device__ __forceinline__ void ldsm4(uint32_t& r0, uint32_t& r1, uint32_t& r2,
                                      uint32_t& r3, uint32_t addr) {
    asm volatile("ldmatrix.sync.aligned.m8n8.x4.shared.b16 {%0,%1,%2,%3}, [%4];"
                 : "=r"(r0), "=r"(r1), "=r"(r2), "=r"(r3) : "r"(addr));
}
__device__ __forceinline__ void mma16816(float* c, const uint32_t* a, const uint32_t* b) {
    asm volatile(
        "mma.sync.aligned.m16n8k16.row.col.f32.bf16.bf16.f32 "
        "{%0,%1,%2,%3}, {%4,%5,%6,%7}, {%8,%9}, {%0,%1,%2,%3};"
        : "+f"(c[0]), "+f"(c[1]), "+f"(c[2]), "+f"(c[3])
        : "r"(a[0]), "r"(a[1]), "r"(a[2]), "r"(a[3]), "r"(b[0]), "r"(b[1]));
}

// ---------------------------------------------------------------------------
// HMMA split-bf16 GEMM: C[M,N] = A @ Bt^T + bias (+elu+1)
// A=[16384,1024] hi/lo, Bt=[N,K]=[1024,1024] hi/lo (weights pre-transposed).
// Grid (EMB/128, ROWS/128) = (8,128). 256 threads, warp tile 64x32.
// ---------------------------------------------------------------------------
__global__ __launch_bounds__(G_THREADS) void gemm_mma(
    const __nv_bfloat16* __restrict__ Ah, const __nv_bfloat16* __restrict__ Al,
    const __nv_bfloat16* __restrict__ Bh, const __nv_bfloat16* __restrict__ Bl,
    const float* __restrict__ bias, float* __restrict__ C, int elu_mode)
{
    extern __shared__ char dsm[];
    const uint32_t dyn = smem_u32(dsm);

    const int tid  = threadIdx.x;
    const int wid  = tid >> 5;
    const int lane = tid & 31;
    const int m0 = blockIdx.y * MT;
    const int n0 = blockIdx.x * NTT;
    const int wm = (wid >> 2) * 64;     // warp row offset (0 / 64)
    const int wn = (wid & 3) * 32;      // warp col offset (0/32/64/96)

    // ---- stage loader: 2048 x 16B granules per chunk ----
    auto load_stage = [&](int ch) {
        const int st = ch % STAGES;
        const uint32_t sb = dyn + (uint32_t)st * STAGE_BYTES;
        const int k0 = ch * KC;
        #pragma unroll
        for (int i = tid; i < 2048; i += G_THREADS) {
            int half = i >> 10;              // 0=A 1=B
            int rem  = i & 1023;
            int hl   = rem >> 9;             // 0=hi 1=lo
            int rr   = (rem >> 2) & 127;
            int g    = rem & 3;
            const __nv_bfloat16* gp =
                half ? (hl ? Bl : Bh) : (hl ? Al : Ah);
            int row = (half ? n0 : m0) + rr;
            uint32_t soff = (uint32_t)(half * 2 + hl) * SZ_ONE
                          + (uint32_t)rr * PITCHB + (uint32_t)g * 16u;
            cp16(sb + soff, gp + (size_t)row * EMB + k0 + g * 8);
        }
        asm volatile("cp.async.commit_group;" ::: "memory");
    };

    float acc[4][4][4];
    #pragma unroll
    for (int i = 0; i < 4; i++)
        #pragma unroll
        for (int j = 0; j < 4; j++)
            #pragma unroll
            for (int q = 0; q < 4; q++) acc[i][j][q] = 0.f;

    // prologue: fill STAGES-1 stages
    #pragma unroll
    for (int s = 0; s < STAGES - 1; s++) load_stage(s);

    for (int ch = 0; ch < KCH; ch++) {
        if (ch + STAGES - 1 < KCH) load_stage(ch + STAGES - 1);
        else asm volatile("cp.async.commit_group;" ::: "memory");
        asm volatile("cp.async.wait_group %0;" :: "n"(STAGES - 1) : "memory");
        __syncthreads();

        const uint32_t sb = dyn + (uint32_t)(ch % STAGES) * STAGE_BYTES;

        #pragma unroll
        for (int ks = 0; ks < KC / 16; ks++) {
            const int kl = ks * 16;
            // lane-address components
            const int a_row = wm + (lane & 7) + ((lane >> 3) & 1) * 8;
            const int a_col = kl + (lane >> 4) * 8;
            const int b_row = wn + (lane & 7) + ((lane >> 4) & 1) * 8;
            const int b_col = kl + ((lane >> 3) & 1) * 8;

            uint32_t ah[4][4], al[4][4];
            #pragma unroll
            for (int fm = 0; fm < 4; fm++) {
                uint32_t off = (uint32_t)(a_row + fm * 16) * PITCHB + (uint32_t)a_col * 2u;
                ldsm4(ah[fm][0], ah[fm][1], ah[fm][2], ah[fm][3], sb + OFF_AH + off);
                ldsm4(al[fm][0], al[fm][1], al[fm][2], al[fm][3], sb + OFF_AL + off);
            }
            uint32_t bh[2][4], bl[2][4];
            #pragma unroll
            for (int fp = 0; fp < 2; fp++) {
                uint32_t off = (uint32_t)(b_row + fp * 16) * PITCHB + (uint32_t)b_col * 2u;
                ldsm4(bh[fp][0], bh[fp][1], bh[fp][2], bh[fp][3], sb + OFF_BH + off);
                ldsm4(bl[fp][0], bl[fp][1], bl[fp][2], bl[fp][3], sb + OFF_BL + off);
            }

            #pragma unroll
            for (int fm = 0; fm < 4; fm++)
                #pragma unroll
                for (int fn = 0; fn < 4; fn++) {
                    const uint32_t* bhp = &bh[fn >> 1][(fn & 1) * 2];
                    const uint32_t* blp = &bl[fn >> 1][(fn & 1) * 2];
                    mma16816(acc[fm][fn], ah[fm], bhp);
                    mma16816(acc[fm][fn], ah[fm], blp);
                    mma16816(acc[fm][fn], al[fm], bhp);
                }
        }
        __syncthreads();
    }

    // ---- epilogue: bias (+elu+1), direct fp32 stores ----
    const int er = lane >> 2;           // 0..7
    const int ec = (lane & 3) * 2;      // 0,2,4,6
    #pragma unroll
    for (int fn = 0; fn < 4; fn++) {
        const int col = n0 + wn + fn * 8 + ec;
        const float b0 = bias[col], b1 = bias[col + 1];
        #pragma unroll
        for (int fm = 0; fm < 4; fm++) {
            const int row = m0 + wm + fm * 16 + er;
            #pragma unroll
            for (int h = 0; h < 2; h++) {       // h=0: rows r, h=1: rows r+8
                float v0 = acc[fm][fn][2 * h + 0] + b0;
                float v1 = acc[fm][fn][2 * h + 1] + b1;
                if (elu_mode) {
                    v0 = (v0 > 0.f) ? (v0 + 1.f) : __expf(v0);
                    v1 = (v1 > 0.f) ? (v1 + 1.f) : __expf(v1);
                }
                *(float2*)(C + (size_t)(row + 8 * h) * EMB + col) = make_float2(v0, v1);
            }
        }
    }
}

// ---------------------------------------------------------------------------
// fp32 -> bf16 hi/lo split (elementwise, float4-vectorized)
// ---------------------------------------------------------------------------
__global__ __launch_bounds__(256) void conv_hilo(
    const float* __restrict__ X, __nv_bfloat16* __restrict__ H,
    __nv_bfloat16* __restrict__ L)
{
    size_t i = ((size_t)blockIdx.x * 256 + threadIdx.x) * 4;
    float4 v = *(const float4*)(X + i);
    __nv_bfloat16 h0 = __float2bfloat16_rn(v.x), h1 = __float2bfloat16_rn(v.y);
    __nv_bfloat16 h2 = __float2bfloat16_rn(v.z), h3 = __float2bfloat16_rn(v.w);
    __nv_bfloat16 l0 = __float2bfloat16_rn(v.x - __bfloat162float(h0));
    __nv_bfloat16 l1 = __float2bfloat16_rn(v.y - __bfloat162float(h1));
    __nv_bfloat16 l2 = __float2bfloat16_rn(v.z - __bfloat162float(h2));
    __nv_bfloat16 l3 = __float2bfloat16_rn(v.w - __bfloat162float(h3));
    ushort4 hv = make_ushort4(__bfloat16_as_ushort(h0), __bfloat16_as_ushort(h1),
                              __bfloat16_as_ushort(h2), __bfloat16_as_ushort(h3));
    ushort4 lv = make_ushort4(__bfloat16_as_ushort(l0), __bfloat16_as_ushort(l1),
                              __bfloat16_as_ushort(l2), __bfloat16_as_ushort(l3));
    *(ushort4*)(H + i) = hv;
    *(ushort4*)(L + i) = lv;
}

// ---------------------------------------------------------------------------
// Weight transpose + hi/lo split: Wt[n][k] = W[k][n]
// ---------------------------------------------------------------------------
__global__ __launch_bounds__(256) void conv_w_t(
    const float* __restrict__ W, __nv_bfloat16* __restrict__ H,
    __nv_bfloat16* __restrict__ L)
{
    __shared__ float tile[32][33];
    const int n0 = blockIdx.x * 32, k0 = blockIdx.y * 32;
    const int tx = threadIdx.x & 31, ty = threadIdx.x >> 5;  // 32x8
    #pragma unroll
    for (int j = 0; j < 32; j += 8)
        tile[ty + j][tx] = W[(size_t)(k0 + ty + j) * EMB + n0 + tx];
    __syncthreads();
    #pragma unroll
    for (int j = 0; j < 32; j += 8) {
        float v = tile[tx][ty + j];
        __nv_bfloat16 h = __float2bfloat16_rn(v);
        __nv_bfloat16 l = __float2bfloat16_rn(v - __bfloat162float(h));
        size_t o = (size_t)(n0 + ty + j) * EMB + k0 + tx;
        H[o] = h; L[o] = l;
    }
}

// ---------------------------------------------------------------------------
// KV summarization (split over S, deterministic reduce)
// ---------------------------------------------------------------------------
#define KVCHUNK 8

__global__ __launch_bounds__(256) void kv_partial()
{
    const int bh = blockIdx.x, sp = blockIdx.y;
    const int b = bh / HEADS, h = bh % HEADS;
    const int t = threadIdx.x;
    const int d = t & 63, g = t >> 6;

    __shared__ float Ks[KVCHUNK][HDIM];
    __shared__ float Vs[KVCHUNK][HDIM];

    float acc[16];
    #pragma unroll
    for (int j = 0; j < 16; j++) acc[j] = 0.f;
    float ksum = 0.f;

    const float* Kbase = g_K + (size_t)b * SEQ * EMB + h * HDIM;
    const float* Vbase = g_V + (size_t)b * SEQ * EMB + h * HDIM;

    const int s_begin = sp * SROWS;
    for (int s0 = s_begin; s0 < s_begin + SROWS; s0 += KVCHUNK) {
        #pragma unroll
        for (int k = 0; k < (KVCHUNK * HDIM) / 256; k++) {
            int idx = t + 256 * k;
            int rr = idx >> 6, cc = idx & 63;
            Ks[rr][cc] = Kbase[(size_t)(s0 + rr) * EMB + cc];
            Vs[rr][cc] = Vbase[(size_t)(s0 + rr) * EMB + cc];
        }
        __syncthreads();
        #pragma unroll
        for (int ss = 0; ss < KVCHUNK; ss++) {
            float kd = Ks[ss][d];
            if (g == 0) ksum += kd;
            #pragma unroll
            for (int j = 0; j < 16; j++)
                acc[j] += kd * Vs[ss][g * 16 + j];
        }
        __syncthreads();
    }

    float* KVp = g_KVp + ((size_t)sp * BH + bh) * HDIM * HDIM;
    #pragma unroll
    for (int j = 0; j < 16; j++)
        KVp[d * HDIM + g * 16 + j] = acc[j];
    if (g == 0) g_Ksump[((size_t)sp * BH + bh) * HDIM + d] = ksum;
}

__global__ __launch_bounds__(256) void kv_reduce()
{
    const int bh = blockIdx.x;
    const int t = threadIdx.x;
    for (int i = t; i < HDIM * HDIM; i += 256) {
        float s = 0.f;
        #pragma unroll
        for (int sp = 0; sp < SPLITS; sp++)
            s += g_KVp[((size_t)sp * BH + bh) * HDIM * HDIM + i];
        g_KV[(size_t)bh * HDIM * HDIM + i] = s;
    }
    if (t < HDIM) {
        float s = 0.f;
        #pragma unroll
        for (int sp = 0; sp < SPLITS; sp++)
            s += g_Ksump[((size_t)sp * BH + bh) * HDIM + t];
        g_Ksum[(size_t)bh * HDIM + t] = s;
    }
}

// ---------------------------------------------------------------------------
// Apply: attn = (Q·KV)/(Q·Ksum + 1e-6) — writes bf16 hi/lo directly (feeds
// the O-projection GEMM, skipping an fp32 round trip)
// ---------------------------------------------------------------------------
__global__ __launch_bounds__(256) void apply_attn()
{
    const int stile = blockIdx.x;
    const int bh = blockIdx.y;
    const int b = bh / HEADS, h = bh % HEADS;
    const int t = threadIdx.x;

    __shared__ float Qs[64][HDIM];
    __shared__ float KVs[HDIM][HDIM];
    __shared__ float Ksums[HDIM];

    const int s0 = stile * 64;
    const float* Qbase = g_Q + (size_t)(b * SEQ + s0) * EMB + h * HDIM;

    #pragma unroll
    for (int k = 0; k < 16; k++) {
        int idx = t + 256 * k;
        int rr = idx >> 6, cc = idx & 63;
        Qs[rr][cc] = Qbase[(size_t)rr * EMB + cc];
        KVs[rr][cc] = g_KV[(size_t)bh * HDIM * HDIM + idx];
    }
    if (t < HDIM) Ksums[t] = g_Ksum[(size_t)bh * HDIM + t];
    __syncthreads();

    const int row = t >> 2;
    const int e0 = (t & 3) * 16;

    float acc[16];
    #pragma unroll
    for (int j = 0; j < 16; j++) acc[j] = 0.f;
    float norm = 0.f;

    #pragma unroll
    for (int dd = 0; dd < HDIM; dd++) {
        float qd = Qs[row][dd];
        norm += qd * Ksums[dd];
        #pragma unroll
        for (int j = 0; j < 16; j++)
            acc[j] += qd * KVs[dd][e0 + j];
    }

    float inv = 1.f / (norm + 1e-6f);
    size_t obase = (size_t)(b * SEQ + s0 + row) * EMB + h * HDIM + e0;
    #pragma unroll
    for (int j = 0; j < 16; j += 4) {
        ushort4 hv, lv;
        unsigned short* hp = (unsigned short*)&hv;
        unsigned short* lp = (unsigned short*)&lv;
        #pragma unroll
        for (int q = 0; q < 4; q++) {
            float v = acc[j + q] * inv;
            __nv_bfloat16 hh = __float2bfloat16_rn(v);
            __nv_bfloat16 ll = __float2bfloat16_rn(v - __bfloat162float(hh));
            hp[q] = __bfloat16_as_ushort(hh);
            lp[q] = __bfloat16_as_ushort(ll);
        }
        *(ushort4*)(g_Xhi + obase + j) = hv;
        *(ushort4*)(g_Xlo + obase + j) = lv;
    }
}

// ---------------------------------------------------------------------------
// Launch
// ---------------------------------------------------------------------------
extern "C" void kernel_launch(void* const* d_in, const int* in_sizes, int n_in,
                              void* d_out, int out_size)
{
    const float* query = (const float*)d_in[0];
    const float* keyv  = (const float*)d_in[1];
    const float* Wq = (const float*)d_in[2];
    const float* bq = (const float*)d_in[3];
    const float* Wk = (const float*)d_in[4];
    const float* bk = (const float*)d_in[5];
    const float* Wv = (const float*)d_in[6];
    const float* bv = (const float*)d_in[7];
    const float* Wo = (const float*)d_in[8];
    const float* bo = (const float*)d_in[9];
    float* out = (float*)d_out;

    float *pQ, *pK, *pV;
    __nv_bfloat16 *pXh, *pXl, *pWqh, *pWql, *pWkh, *pWkl, *pWvh, *pWvl, *pWoh, *pWol;
    cudaGetSymbolAddress((void**)&pQ, g_Q);
    cudaGetSymbolAddress((void**)&pK, g_K);
    cudaGetSymbolAddress((void**)&pV, g_V);
    cudaGetSymbolAddress((void**)&pXh, g_Xhi);
    cudaGetSymbolAddress((void**)&pXl, g_Xlo);
    cudaGetSymbolAddress((void**)&pWqh, g_Wqh);
    cudaGetSymbolAddress((void**)&pWql, g_Wql);
    cudaGetSymbolAddress((void**)&pWkh, g_Wkh);
    cudaGetSymbolAddress((void**)&pWkl, g_Wkl);
    cudaGetSymbolAddress((void**)&pWvh, g_Wvh);
    cudaGetSymbolAddress((void**)&pWvl, g_Wvl);
    cudaGetSymbolAddress((void**)&pWoh, g_Woh);
    cudaGetSymbolAddress((void**)&pWol, g_Wol);

    static bool attr_set = false;
    if (!attr_set) {
        cudaFuncSetAttribute(gemm_mma, cudaFuncAttributeMaxDynamicSharedMemorySize, SMEM_DYN);
        attr_set = true;
    }

    const dim3 wgrid(EMB / 32, EMB / 32);              // (32, 32)
    const dim3 ggrid(EMB / NTT, ROWS / MT);            // (8, 128)
    const int conv_blocks = (int)(((size_t)ROWS * EMB / 4) / 256);  // 16384

    // Weight transpose + split
    conv_w_t<<<wgrid, 256>>>(Wq, pWqh, pWql);
    conv_w_t<<<wgrid, 256>>>(Wk, pWkh, pWkl);
    conv_w_t<<<wgrid, 256>>>(Wv, pWvh, pWvl);
    conv_w_t<<<wgrid, 256>>>(Wo, pWoh, pWol);

    // Q projection (elu+1 fused)
    conv_hilo<<<conv_blocks, 256>>>(query, pXh, pXl);
    gemm_mma<<<ggrid, G_THREADS, SMEM_DYN>>>(pXh, pXl, pWqh, pWql, bq, pQ, 1);

    // K/V projections (share key_value conversion)
    conv_hilo<<<conv_blocks, 256>>>(keyv, pXh, pXl);
    gemm_mma<<<ggrid, G_THREADS, SMEM_DYN>>>(pXh, pXl, pWkh, pWkl, bk, pK, 1);
    gemm_mma<<<ggrid, G_THREADS, SMEM_DYN>>>(pXh, pXl, pWvh, pWvl, bv, pV, 0);

    // Linear-attention core (fp32)
    kv_partial<<<dim3(BH, SPLITS), 256>>>();
    kv_reduce<<<BH, 256>>>();
    apply_attn<<<dim3(SEQ / 64, BH), 256>>>();   // writes hi/lo into g_Xhi/g_Xlo

    // Output projection
    gemm_mma<<<ggrid, G_THREADS, SMEM_DYN>>>(pXh, pXl, pWoh, pWol, bo, out, 0);
}